// round 11
// baseline (speedup 1.0000x reference)
#include <cuda_runtime.h>
#include <cstdint>

#define MAXB 64

// ---------------- global accumulators (zero-init; reset by last block) ------
__device__ double       g_ce_acc;
__device__ float        g_reg_acc[MAXB];
__device__ float        g_ldm_acc[MAXB];
__device__ int          g_npos_acc[MAXB];
__device__ unsigned int g_done;

__device__ __forceinline__ float smooth_l1(float d) {
    float a = fabsf(d);
    return a < 1.f ? 0.5f * d * d : a - 0.5f;
}

// GT: compile-time G (0 => runtime). APT: anchors per thread.
template<int GT, int APT>
__global__ void __launch_bounds__(256) rf_fused_kernel(
    const float* __restrict__ pred_cls,
    const float* __restrict__ pred_bbox,
    const float* __restrict__ pred_ldm,
    const float* __restrict__ anchors,
    const float* __restrict__ gt_boxes,
    const float* __restrict__ gt_ldm,
    float* __restrict__ out,
    int B, int A, int G_rt)
{
    constexpr int GMAX = (GT > 0) ? GT : 64;
    const int G = (GT > 0) ? GT : G_rt;

    __shared__ float4 sgb[GMAX];        // gt boxes
    __shared__ float  ssz[GMAX];        // gt areas
    __shared__ float  sgl[GMAX * 10];   // gt landmarks

    const int b   = blockIdx.y;
    const int tid = threadIdx.x;

    if (tid < G) {
        float4 gbx = *(const float4*)(gt_boxes + ((size_t)b * G + tid) * 4);
        sgb[tid] = gbx;
        ssz[tid] = (gbx.z - gbx.x) * (gbx.w - gbx.y);
    }
    for (int i = tid; i < G * 10; i += blockDim.x)
        sgl[i] = gt_ldm[(size_t)b * G * 10 + i];
    __syncthreads();

    const int a0 = blockIdx.x * (blockDim.x * APT) + tid;

    float ax0[APT], ay0[APT], ax1[APT], ay1[APT], sa[APT];
    float bi[APT], sb[APT];    // best inter, best (area_a + area_g)
    int   bg[APT];
    bool  valid[APT];

    #pragma unroll
    for (int k = 0; k < APT; ++k) {
        int a = a0 + k * blockDim.x;
        valid[k] = (a < A);
        float4 an = valid[k] ? *(const float4*)(anchors + (size_t)a * 4)
                             : make_float4(0.f, 0.f, 1.f, 1.f);
        ax0[k] = an.x; ay0[k] = an.y; ax1[k] = an.z; ay1[k] = an.w;
        sa[k]  = (an.z - an.x) * (an.w - an.y);
        bi[k]  = 0.f;          // iou_best = 0
        sb[k]  = 1.f;          // any positive value; 0*s > in*1 never lies
        bg[k]  = 0;
    }

    // Division-free IoU argmax: iou_new > iou_best  <=>  in*sb > bi*s,
    // exact identity: union + inter = area_a + area_g = s.
    // Ternary selects -> FSEL (pred-as-data, 4cyc) instead of @P guards (13cyc).
    #pragma unroll 4
    for (int g = 0; g < G; ++g) {
        const float4 gb = sgb[g];
        const float  sg = ssz[g];
        #pragma unroll
        for (int k = 0; k < APT; ++k) {
            float iw = fmaxf(fminf(ax1[k], gb.z) - fmaxf(ax0[k], gb.x), 0.f);
            float ih = fmaxf(fminf(ay1[k], gb.w) - fmaxf(ay0[k], gb.y), 0.f);
            float in = iw * ih;
            float s  = sa[k] + sg;
            bool  c  = in * sb[k] > bi[k] * s;
            bi[k] = c ? in : bi[k];
            sb[k] = c ? s  : sb[k];
            bg[k] = c ? g  : bg[k];
        }
    }

    float ce_sum = 0.f;
    #pragma unroll
    for (int k = 0; k < APT; ++k) {
        if (!valid[k]) continue;
        int    a    = a0 + k * blockDim.x;
        size_t base = (size_t)b * A + a;
        // iou >= 0.5  <=>  3*bi >= sb
        bool pos = (3.f * bi[k] >= sb[k]);

        // stable 2-class log-softmax CE (fast path: arg of log in (1,2])
        float2 c  = *(const float2*)(pred_cls + base * 2);
        float  mx = fmaxf(c.x, c.y);
        float  lse = mx + __logf(1.f + __expf(fminf(c.x, c.y) - mx));
        ce_sum += lse - (pos ? c.y : c.x);

        if (pos) {   // rare path: only now touch pred_bbox / pred_landmarks
            float aw = ax1[k] - ax0[k], ah = ay1[k] - ay0[k];
            float acx = ax0[k] + 0.5f * aw, acy = ay0[k] + 0.5f * ah;
            float4 gb = sgb[bg[k]];
            float gw = gb.z - gb.x, gh = gb.w - gb.y;
            float gcx = gb.x + 0.5f * gw, gcy = gb.y + 0.5f * gh;

            float4 pb = *(const float4*)(pred_bbox + base * 4);
            float r = smooth_l1(pb.x - (gcx - acx) / aw)
                    + smooth_l1(pb.y - (gcy - acy) / ah)
                    + smooth_l1(pb.z - logf(gw / aw))
                    + smooth_l1(pb.w - logf(gh / ah));

            float l = 0.f;
            const float* pl = pred_ldm + base * 10;
            const float* gl = sgl + bg[k] * 10;
            #pragma unroll
            for (int j = 0; j < 10; ++j) l += smooth_l1(pl[j] - gl[j]);

            atomicAdd(&g_reg_acc[b], r);
            atomicAdd(&g_ldm_acc[b], l);
            atomicAdd(&g_npos_acc[b], 1);
        }
    }

    // block reduction of CE -> one double atomic per block
    #pragma unroll
    for (int o = 16; o > 0; o >>= 1)
        ce_sum += __shfl_down_sync(0xffffffffu, ce_sum, o);
    __shared__ float wsum[8];
    int w = tid >> 5, lane = tid & 31;
    if (lane == 0) wsum[w] = ce_sum;
    __syncthreads();
    if (w == 0) {
        int nw = blockDim.x >> 5;
        float v = (lane < nw) ? wsum[lane] : 0.f;
        #pragma unroll
        for (int o = 4; o > 0; o >>= 1)
            v += __shfl_down_sync(0xffffffffu, v, o);
        if (lane == 0) atomicAdd(&g_ce_acc, (double)v);
    }

    // ---- last-block finalize + state reset (keeps graph replays deterministic)
    __syncthreads();                 // all this block's atomics issued
    __shared__ bool s_last;
    if (tid == 0) {
        __threadfence();             // publish before arrival
        unsigned total = gridDim.x * gridDim.y;
        s_last = (atomicAdd(&g_done, 1u) == total - 1u);
    }
    __syncthreads();
    if (s_last && tid == 0) {
        __threadfence();             // acquire all blocks' contributions
        double ce = *(volatile double*)&g_ce_acc;
        float cls = (float)(ce / ((double)A * (double)B));
        float reg = 0.f, ldm = 0.f;
        for (int bb = 0; bb < B; ++bb) {
            int np = *(volatile int*)&g_npos_acc[bb];
            if (np > 0) {
                reg += (*(volatile float*)&g_reg_acc[bb]) / ((float)np * 4.0f);
                ldm += (*(volatile float*)&g_ldm_acc[bb]) / ((float)np * 10.0f);
            }
        }
        reg /= (float)B;
        ldm /= (float)B;
        out[0] = cls + reg + ldm;
        out[1] = cls;
        out[2] = reg;
        out[3] = ldm;
        // reset scratch for the next graph replay
        g_ce_acc = 0.0;
        for (int bb = 0; bb < MAXB; ++bb) {
            g_reg_acc[bb] = 0.f; g_ldm_acc[bb] = 0.f; g_npos_acc[bb] = 0;
        }
        __threadfence();
        g_done = 0;
    }
}

extern "C" void kernel_launch(void* const* d_in, const int* in_sizes, int n_in,
                              void* d_out, int out_size) {
    const float* pred_cls  = (const float*)d_in[0];
    const float* pred_bbox = (const float*)d_in[1];
    const float* pred_ldm  = (const float*)d_in[2];
    const float* anchors   = (const float*)d_in[3];
    const float* gt_boxes  = (const float*)d_in[4];
    const float* gt_ldm    = (const float*)d_in[5];
    float* out = (float*)d_out;

    const int A = in_sizes[3] / 4;
    const int B = (A > 0) ? in_sizes[0] / (2 * A) : 1;
    const int G = (B > 0) ? in_sizes[4] / (4 * B) : 1;

    constexpr int APT = 4;
    const int threads = 256;
    dim3 grid((A + threads * APT - 1) / (threads * APT), B);

    if (G == 32)
        rf_fused_kernel<32, APT><<<grid, threads>>>(
            pred_cls, pred_bbox, pred_ldm, anchors, gt_boxes, gt_ldm, out, B, A, G);
    else
        rf_fused_kernel<0, APT><<<grid, threads>>>(
            pred_cls, pred_bbox, pred_ldm, anchors, gt_boxes, gt_ldm, out, B, A, G);
}

// round 12
// speedup vs baseline: 1.0268x; 1.0268x over previous
#include <cuda_runtime.h>
#include <cstdint>

#define MAXB 64

// ---------------- global accumulators (zero-init; reset by last block) ------
__device__ double       g_ce_acc;
__device__ float        g_reg_acc[MAXB];
__device__ float        g_ldm_acc[MAXB];
__device__ int          g_npos_acc[MAXB];
__device__ unsigned int g_done;

__device__ __forceinline__ float smooth_l1(float d) {
    float a = fabsf(d);
    return a < 1.f ? 0.5f * d * d : a - 0.5f;
}

// GT: compile-time G (0 => runtime). APT: anchors per thread.
template<int GT, int APT>
__global__ void __launch_bounds__(256) rf_fused_kernel(
    const float* __restrict__ pred_cls,
    const float* __restrict__ pred_bbox,
    const float* __restrict__ pred_ldm,
    const float* __restrict__ anchors,
    const float* __restrict__ gt_boxes,
    const float* __restrict__ gt_ldm,
    float* __restrict__ out,
    int B, int A, int G_rt)
{
    constexpr int GMAX = (GT > 0) ? GT : 64;
    const int G = (GT > 0) ? GT : G_rt;

    __shared__ float4 sgb[GMAX];        // gt boxes
    __shared__ float  ssz[GMAX];        // gt areas
    __shared__ float  sgl[GMAX * 10];   // gt landmarks

    const int b   = blockIdx.y;
    const int tid = threadIdx.x;

    if (tid < G) {
        float4 gbx = *(const float4*)(gt_boxes + ((size_t)b * G + tid) * 4);
        sgb[tid] = gbx;
        ssz[tid] = (gbx.z - gbx.x) * (gbx.w - gbx.y);
    }
    for (int i = tid; i < G * 10; i += blockDim.x)
        sgl[i] = gt_ldm[(size_t)b * G * 10 + i];
    __syncthreads();

    const int a0 = blockIdx.x * (blockDim.x * APT) + tid;

    float ax0[APT], ay0[APT], ax1[APT], ay1[APT], sa[APT];
    float bi[APT], sb[APT];    // best inter, best (area_a + area_g)
    int   bg[APT];

    #pragma unroll
    for (int k = 0; k < APT; ++k) {
        int a = a0 + k * blockDim.x;
        float4 an = (a < A) ? *(const float4*)(anchors + (size_t)a * 4)
                            : make_float4(0.f, 0.f, 1.f, 1.f);
        ax0[k] = an.x; ay0[k] = an.y; ax1[k] = an.z; ay1[k] = an.w;
        sa[k]  = (an.z - an.x) * (an.w - an.y);
        bi[k]  = 0.f;          // iou_best = 0
        sb[k]  = 1.f;          // any positive value; 0*s > in*1 never lies
        bg[k]  = 0;
    }

    // Division-free IoU argmax: iou_new > iou_best  <=>  in*sb > bi*s,
    // exact identity: union + inter = area_a + area_g = s.
    #pragma unroll 4
    for (int g = 0; g < G; ++g) {
        const float4 gb = sgb[g];
        const float  sg = ssz[g];
        #pragma unroll
        for (int k = 0; k < APT; ++k) {
            float iw = fmaxf(fminf(ax1[k], gb.z) - fmaxf(ax0[k], gb.x), 0.f);
            float ih = fmaxf(fminf(ay1[k], gb.w) - fmaxf(ay0[k], gb.y), 0.f);
            float in = iw * ih;
            float s  = sa[k] + sg;
            bool  c  = in * sb[k] > bi[k] * s;
            bi[k] = c ? in : bi[k];
            sb[k] = c ? s  : sb[k];
            bg[k] = c ? g  : bg[k];
        }
    }

    float ce_sum = 0.f;
    #pragma unroll
    for (int k = 0; k < APT; ++k) {
        int a = a0 + k * blockDim.x;
        if (a >= A) continue;
        size_t base = (size_t)b * A + a;
        // iou >= 0.5  <=>  3*bi >= sb
        bool pos = (3.f * bi[k] >= sb[k]);

        // stable 2-class log-softmax CE (fast path: arg of log in (1,2])
        float2 c  = *(const float2*)(pred_cls + base * 2);
        float  mx = fmaxf(c.x, c.y);
        float  lse = mx + __logf(1.f + __expf(fminf(c.x, c.y) - mx));
        ce_sum += lse - (pos ? c.y : c.x);

        if (pos) {   // rare path: only now touch pred_bbox / pred_landmarks
            float aw = ax1[k] - ax0[k], ah = ay1[k] - ay0[k];
            float acx = ax0[k] + 0.5f * aw, acy = ay0[k] + 0.5f * ah;
            float4 gb = sgb[bg[k]];
            float gw = gb.z - gb.x, gh = gb.w - gb.y;
            float gcx = gb.x + 0.5f * gw, gcy = gb.y + 0.5f * gh;

            float4 pb = *(const float4*)(pred_bbox + base * 4);
            float r = smooth_l1(pb.x - (gcx - acx) / aw)
                    + smooth_l1(pb.y - (gcy - acy) / ah)
                    + smooth_l1(pb.z - logf(gw / aw))
                    + smooth_l1(pb.w - logf(gh / ah));

            float l = 0.f;
            const float* pl = pred_ldm + base * 10;
            const float* gl = sgl + bg[k] * 10;
            #pragma unroll
            for (int j = 0; j < 10; ++j) l += smooth_l1(pl[j] - gl[j]);

            atomicAdd(&g_reg_acc[b], r);
            atomicAdd(&g_ldm_acc[b], l);
            atomicAdd(&g_npos_acc[b], 1);
        }
    }

    // block reduction of CE -> one double atomic per block
    #pragma unroll
    for (int o = 16; o > 0; o >>= 1)
        ce_sum += __shfl_down_sync(0xffffffffu, ce_sum, o);
    __shared__ float wsum[8];
    int w = tid >> 5, lane = tid & 31;
    if (lane == 0) wsum[w] = ce_sum;
    __syncthreads();
    if (w == 0) {
        int nw = blockDim.x >> 5;
        float v = (lane < nw) ? wsum[lane] : 0.f;
        #pragma unroll
        for (int o = 4; o > 0; o >>= 1)
            v += __shfl_down_sync(0xffffffffu, v, o);
        if (lane == 0) atomicAdd(&g_ce_acc, (double)v);
    }

    // ---- last-block finalize + state reset (keeps graph replays deterministic)
    __syncthreads();                 // all this block's atomics issued
    __shared__ bool s_last;
    if (tid == 0) {
        __threadfence();             // publish before arrival
        unsigned total = gridDim.x * gridDim.y;
        s_last = (atomicAdd(&g_done, 1u) == total - 1u);
    }
    __syncthreads();
    if (s_last && tid == 0) {
        __threadfence();             // acquire all blocks' contributions
        double ce = *(volatile double*)&g_ce_acc;
        float cls = (float)(ce / ((double)A * (double)B));
        float reg = 0.f, ldm = 0.f;
        for (int bb = 0; bb < B; ++bb) {
            int np = *(volatile int*)&g_npos_acc[bb];
            if (np > 0) {
                reg += (*(volatile float*)&g_reg_acc[bb]) / ((float)np * 4.0f);
                ldm += (*(volatile float*)&g_ldm_acc[bb]) / ((float)np * 10.0f);
            }
        }
        reg /= (float)B;
        ldm /= (float)B;
        out[0] = cls + reg + ldm;
        out[1] = cls;
        out[2] = reg;
        out[3] = ldm;
        // reset scratch for the next graph replay
        g_ce_acc = 0.0;
        for (int bb = 0; bb < MAXB; ++bb) {
            g_reg_acc[bb] = 0.f; g_ldm_acc[bb] = 0.f; g_npos_acc[bb] = 0;
        }
        __threadfence();
        g_done = 0;
    }
}

extern "C" void kernel_launch(void* const* d_in, const int* in_sizes, int n_in,
                              void* d_out, int out_size) {
    const float* pred_cls  = (const float*)d_in[0];
    const float* pred_bbox = (const float*)d_in[1];
    const float* pred_ldm  = (const float*)d_in[2];
    const float* anchors   = (const float*)d_in[3];
    const float* gt_boxes  = (const float*)d_in[4];
    const float* gt_ldm    = (const float*)d_in[5];
    float* out = (float*)d_out;

    const int A = in_sizes[3] / 4;
    const int B = (A > 0) ? in_sizes[0] / (2 * A) : 1;
    const int G = (B > 0) ? in_sizes[4] / (4 * B) : 1;

    constexpr int APT = 2;               // was 4: cut live state, stop spills
    const int threads = 256;
    dim3 grid((A + threads * APT - 1) / (threads * APT), B);

    if (G == 32)
        rf_fused_kernel<32, APT><<<grid, threads>>>(
            pred_cls, pred_bbox, pred_ldm, anchors, gt_boxes, gt_ldm, out, B, A, G);
    else
        rf_fused_kernel<0, APT><<<grid, threads>>>(
            pred_cls, pred_bbox, pred_ldm, anchors, gt_boxes, gt_ldm, out, B, A, G);
}

// round 16
// speedup vs baseline: 1.0282x; 1.0014x over previous
#include <cuda_runtime.h>
#include <cstdint>

#define MAXB 64

// ---------------- global accumulators (zero-init; reset by last block) ------
__device__ double       g_ce_acc;
__device__ float        g_reg_acc[MAXB];
__device__ float        g_ldm_acc[MAXB];
__device__ int          g_npos_acc[MAXB];
__device__ unsigned int g_done;

__device__ __forceinline__ float smooth_l1(float d) {
    float a = fabsf(d);
    return a < 1.f ? 0.5f * d * d : a - 0.5f;
}

// One IoU-argmax step for gt box gb/area sg against all APT anchor chains.
#define IOU_STEP(gb, sg, gidx)                                                 \
    {                                                                          \
        _Pragma("unroll")                                                      \
        for (int k = 0; k < APT; ++k) {                                        \
            float iw = fmaxf(fminf(ax1[k], (gb).z) - fmaxf(ax0[k], (gb).x), 0.f); \
            float ih = fmaxf(fminf(ay1[k], (gb).w) - fmaxf(ay0[k], (gb).y), 0.f); \
            float in = iw * ih;                                                \
            float s  = sa[k] + (sg);                                           \
            bool  c  = in * sb[k] > bi[k] * s;                                 \
            bi[k] = c ? in : bi[k];                                            \
            sb[k] = c ? s  : sb[k];                                            \
            bg[k] = c ? (gidx) : bg[k];                                        \
        }                                                                      \
    }

// GT: compile-time G (0 => runtime). APT: anchors per thread.
template<int GT, int APT>
__global__ void __launch_bounds__(256) rf_fused_kernel(
    const float* __restrict__ pred_cls,
    const float* __restrict__ pred_bbox,
    const float* __restrict__ pred_ldm,
    const float* __restrict__ anchors,
    const float* __restrict__ gt_boxes,
    const float* __restrict__ gt_ldm,
    float* __restrict__ out,
    int B, int A, int G_rt)
{
    constexpr int GMAX = (GT > 0) ? GT : 64;
    const int G = (GT > 0) ? GT : G_rt;

    __shared__ float4 sgb[GMAX];        // gt boxes
    __shared__ float  ssz[GMAX];        // gt areas
    __shared__ float  sgl[GMAX * 10];   // gt landmarks

    const int b   = blockIdx.y;
    const int tid = threadIdx.x;

    if (tid < G) {
        float4 gbx = *(const float4*)(gt_boxes + ((size_t)b * G + tid) * 4);
        sgb[tid] = gbx;
        ssz[tid] = (gbx.z - gbx.x) * (gbx.w - gbx.y);
    }
    for (int i = tid; i < G * 10; i += blockDim.x)
        sgl[i] = gt_ldm[(size_t)b * G * 10 + i];
    __syncthreads();

    const int a0 = blockIdx.x * (blockDim.x * APT) + tid;

    float ax0[APT], ay0[APT], ax1[APT], ay1[APT], sa[APT];
    float bi[APT], sb[APT];    // best inter, best (area_a + area_g)
    int   bg[APT];

    #pragma unroll
    for (int k = 0; k < APT; ++k) {
        int a = a0 + k * blockDim.x;
        float4 an = (a < A) ? *(const float4*)(anchors + (size_t)a * 4)
                            : make_float4(0.f, 0.f, 1.f, 1.f);
        ax0[k] = an.x; ay0[k] = an.y; ax1[k] = an.z; ay1[k] = an.w;
        sa[k]  = (an.z - an.x) * (an.w - an.y);
        bi[k]  = 0.f;          // iou_best = 0
        sb[k]  = 1.f;          // any positive value; 0*s > in*1 never lies
        bg[k]  = 0;
    }

    // Division-free IoU argmax: iou_new > iou_best  <=>  in*sb > bi*s,
    // exact identity: union + inter = area_a + area_g = s.
    // Software-pipelined gt loads: prefetch next 2 gt into registers while
    // computing the current 2 -> LDS results are ready long before use,
    // breaking the lockstep scoreboard-wait convoy across warps.
    if (GT > 0 && (GT & (GT - 1)) == 0 && GT >= 4) {
        float4 gbA = sgb[0]; float sgA = ssz[0];
        float4 gbB = sgb[1]; float sgB = ssz[1];
        #pragma unroll 4
        for (int g = 0; g < GT; g += 2) {
            int gn = (g + 2) & (GT - 1);          // wraps to 0 on last iter (harmless)
            float4 nbA = sgb[gn];     float nsA = ssz[gn];
            float4 nbB = sgb[gn + 1]; float nsB = ssz[gn + 1];
            IOU_STEP(gbA, sgA, g)
            IOU_STEP(gbB, sgB, g + 1)
            gbA = nbA; sgA = nsA; gbB = nbB; sgB = nsB;
        }
    } else {
        #pragma unroll 4
        for (int g = 0; g < G; ++g) {
            const float4 gb = sgb[g];
            const float  sg = ssz[g];
            IOU_STEP(gb, sg, g)
        }
    }

    float ce_sum = 0.f;
    #pragma unroll
    for (int k = 0; k < APT; ++k) {
        int a = a0 + k * blockDim.x;
        if (a >= A) continue;
        size_t base = (size_t)b * A + a;
        // iou >= 0.5  <=>  3*bi >= sb
        bool pos = (3.f * bi[k] >= sb[k]);

        // stable 2-class log-softmax CE (fast path: arg of log in (1,2])
        float2 c  = *(const float2*)(pred_cls + base * 2);
        float  mx = fmaxf(c.x, c.y);
        float  lse = mx + __logf(1.f + __expf(fminf(c.x, c.y) - mx));
        ce_sum += lse - (pos ? c.y : c.x);

        if (pos) {   // rare path: only now touch pred_bbox / pred_landmarks
            float aw = ax1[k] - ax0[k], ah = ay1[k] - ay0[k];
            float acx = ax0[k] + 0.5f * aw, acy = ay0[k] + 0.5f * ah;
            float4 gb = sgb[bg[k]];
            float gw = gb.z - gb.x, gh = gb.w - gb.y;
            float gcx = gb.x + 0.5f * gw, gcy = gb.y + 0.5f * gh;

            float4 pb = *(const float4*)(pred_bbox + base * 4);
            float r = smooth_l1(pb.x - (gcx - acx) / aw)
                    + smooth_l1(pb.y - (gcy - acy) / ah)
                    + smooth_l1(pb.z - logf(gw / aw))
                    + smooth_l1(pb.w - logf(gh / ah));

            float l = 0.f;
            const float* pl = pred_ldm + base * 10;
            const float* gl = sgl + bg[k] * 10;
            #pragma unroll
            for (int j = 0; j < 10; ++j) l += smooth_l1(pl[j] - gl[j]);

            atomicAdd(&g_reg_acc[b], r);
            atomicAdd(&g_ldm_acc[b], l);
            atomicAdd(&g_npos_acc[b], 1);
        }
    }

    // block reduction of CE -> one double atomic per block
    #pragma unroll
    for (int o = 16; o > 0; o >>= 1)
        ce_sum += __shfl_down_sync(0xffffffffu, ce_sum, o);
    __shared__ float wsum[8];
    int w = tid >> 5, lane = tid & 31;
    if (lane == 0) wsum[w] = ce_sum;
    __syncthreads();
    if (w == 0) {
        int nw = blockDim.x >> 5;
        float v = (lane < nw) ? wsum[lane] : 0.f;
        #pragma unroll
        for (int o = 4; o > 0; o >>= 1)
            v += __shfl_down_sync(0xffffffffu, v, o);
        if (lane == 0) atomicAdd(&g_ce_acc, (double)v);
    }

    // ---- last-block finalize + state reset (keeps graph replays deterministic)
    __syncthreads();                 // all this block's atomics issued
    __shared__ bool s_last;
    if (tid == 0) {
        __threadfence();             // publish before arrival
        unsigned total = gridDim.x * gridDim.y;
        s_last = (atomicAdd(&g_done, 1u) == total - 1u);
    }
    __syncthreads();
    if (s_last && tid == 0) {
        __threadfence();             // acquire all blocks' contributions
        double ce = *(volatile double*)&g_ce_acc;
        float cls = (float)(ce / ((double)A * (double)B));
        float reg = 0.f, ldm = 0.f;
        for (int bb = 0; bb < B; ++bb) {
            int np = *(volatile int*)&g_npos_acc[bb];
            if (np > 0) {
                reg += (*(volatile float*)&g_reg_acc[bb]) / ((float)np * 4.0f);
                ldm += (*(volatile float*)&g_ldm_acc[bb]) / ((float)np * 10.0f);
            }
        }
        reg /= (float)B;
        ldm /= (float)B;
        out[0] = cls + reg + ldm;
        out[1] = cls;
        out[2] = reg;
        out[3] = ldm;
        // reset scratch for the next graph replay
        g_ce_acc = 0.0;
        for (int bb = 0; bb < MAXB; ++bb) {
            g_reg_acc[bb] = 0.f; g_ldm_acc[bb] = 0.f; g_npos_acc[bb] = 0;
        }
        __threadfence();
        g_done = 0;
    }
}

extern "C" void kernel_launch(void* const* d_in, const int* in_sizes, int n_in,
                              void* d_out, int out_size) {
    const float* pred_cls  = (const float*)d_in[0];
    const float* pred_bbox = (const float*)d_in[1];
    const float* pred_ldm  = (const float*)d_in[2];
    const float* anchors   = (const float*)d_in[3];
    const float* gt_boxes  = (const float*)d_in[4];
    const float* gt_ldm    = (const float*)d_in[5];
    float* out = (float*)d_out;

    const int A = in_sizes[3] / 4;
    const int B = (A > 0) ? in_sizes[0] / (2 * A) : 1;
    const int G = (B > 0) ? in_sizes[4] / (4 * B) : 1;

    constexpr int APT = 2;
    const int threads = 256;
    dim3 grid((A + threads * APT - 1) / (threads * APT), B);

    if (G == 32)
        rf_fused_kernel<32, APT><<<grid, threads>>>(
            pred_cls, pred_bbox, pred_ldm, anchors, gt_boxes, gt_ldm, out, B, A, G);
    else
        rf_fused_kernel<0, APT><<<grid, threads>>>(
            pred_cls, pred_bbox, pred_ldm, anchors, gt_boxes, gt_ldm, out, B, A, G);
}